// round 2
// baseline (speedup 1.0000x reference)
#include <cuda_runtime.h>
#include <math.h>

#define NB      512     // total batch (8*16*4)
#define CHUNK   257
#define NCOEF   771
#define NFRAMES 128
#define STEP    256
#define NSAMP   32768

// Scratch (allocation-free rule: __device__ globals)
__device__ float2 g_spec[(size_t)NB * NFRAMES * CHUNK];  // ~134.7 MB, w_k folded in
__device__ float  g_inv[NB];

typedef unsigned long long u64;

__device__ __forceinline__ u64 pk(float lo, float hi) {
    u64 r; asm("mov.b64 %0,{%1,%2};" : "=l"(r) : "f"(lo), "f"(hi)); return r;
}
__device__ __forceinline__ void upk(u64 v, float& lo, float& hi) {
    asm("mov.b64 {%0,%1},%2;" : "=f"(lo), "=f"(hi) : "l"(v));
}
#define FMA2(d, a, b, c) asm("fma.rn.f32x2 %0,%1,%2,%3;" : "=l"(d) : "l"(a), "l"(b), "l"(c))
#define MUL2(d, a, b)    asm("mul.rn.f32x2 %0,%1,%2;"    : "=l"(d) : "l"(a), "l"(b))

// ---------------------------------------------------------------------------
// Kernel A: GEMM (relu(sel) @ items) fused with activation + per-frame
// complex-rotator recurrence. One thread per spectral bin k, 8 batches/CTA.
// ---------------------------------------------------------------------------
#define BPB 8
__global__ void __launch_bounds__(288) kA(const float* __restrict__ sel,
                                          const float* __restrict__ items) {
    __shared__ float sh_sel[BPB * 512];
    const int tid = threadIdx.x;
    const int b0  = blockIdx.x * BPB;

    for (int idx = tid; idx < BPB * 512; idx += 288) {
        float v = sel[b0 * 512 + idx];
        sh_sel[idx] = v > 0.f ? v : 0.f;
    }
    __syncthreads();

    const int k = tid;
    if (k >= CHUNK) return;

    float am[BPB], ap[BPB], as_[BPB];
#pragma unroll
    for (int b = 0; b < BPB; b++) { am[b] = 0.f; ap[b] = 0.f; as_[b] = 0.f; }

    for (int i = 0; i < 512; i++) {
        const float i0 = items[i * NCOEF + k];
        const float i1 = items[i * NCOEF + CHUNK + k];
        const float i2 = items[i * NCOEF + 2 * CHUNK + k];
#pragma unroll
        for (int b = 0; b < BPB; b++) {
            const float s = sh_sel[b * 512 + i];
            am[b]  = fmaf(s, i0, am[b]);
            ap[b]  = fmaf(s, i1, ap[b]);
            as_[b] = fmaf(s, i2, as_[b]);
        }
    }

    // irfft halfcomplex weights folded into spectrum.
    const float w = (k == 0 || k == 256) ? (1.f / 512.f) : (2.f / 512.f);

#pragma unroll 1
    for (int b = 0; b < BPB; b++) {
        const float m  = fmaf(1.f / (1.f + expf(-am[b])), 0.9999f * 0.5f, 0.5f);
        const float ph = tanhf(ap[b]) * 3.14159265358979323846f;
        const float st = 1.f / (1.f + expf(-as_[b]));
        float sn, cs;
        sincosf(ph, &sn, &cs);
        const float rRe = m * cs, rIm = m * sn;   // ratio r = m * e^{i ph}
        float cRe = st * rRe, cIm = st * rIm;      // t = 1 term: st * r
        size_t base = ((size_t)(b0 + b) * NFRAMES) * CHUNK + k;
        for (int f = 0; f < NFRAMES; f++) {
            g_spec[base + (size_t)f * CHUNK] = make_float2(w * cRe, w * cIm);
            const float nRe = fmaf(cRe, rRe, -(cIm * rIm));
            const float nIm = fmaf(cRe, rIm,  (cIm * rRe));
            cRe = nRe; cIm = nIm;
        }
    }
}

// ---------------------------------------------------------------------------
// Kernel B (v2): per output block of 256 samples, evaluate two half-frame
// iDFT sums (frame j at n, frame j-1 at n+256) with a PACKED complex rotator
// over consecutive bin pairs (k, k+1) using fma.rn.f32x2 — 2x fma-pipe
// throughput vs scalar. (-1)^k for the shifted half is folded into shared
// at load time. Im at k=0 / k=256 handled by sin=0 / explicit zeroing.
// ---------------------------------------------------------------------------
__global__ void __launch_bounds__(256) kB(float* __restrict__ out) {
    // 260 floats per stream, pairs viewed as u64 (broadcast LDS.64)
    __shared__ __align__(16) float sfRe[260], sfIm[260], spRe[260], spIm[260];
    const int tid = threadIdx.x;
    const int j   = blockIdx.x;   // frame index 0..127
    const int b   = blockIdx.y;

    const float2* specF = g_spec + ((size_t)b * NFRAMES + j) * CHUNK;
    const float2* specP = specF - CHUNK;
    for (int k = tid; k < 260; k += 256) {
        float fre = 0.f, fim = 0.f, pre = 0.f, pim = 0.f;
        if (k < 257) {
            const float2 a = specF[k];
            fre = a.x; fim = a.y;
            if (j > 0) {
                const float2 p = specP[k];
                const float sgn = (k & 1) ? -1.f : 1.f;  // fold (-1)^k for shifted half
                pre = p.x * sgn; pim = p.y * sgn;
            }
            if (k == 256) { fim = 0.f; pim = 0.f; }      // halfcomplex Nyquist
        }
        sfRe[k] = fre; sfIm[k] = fim; spRe[k] = pre; spIm[k] = pim;
    }
    __syncthreads();

    // Rotator angle per bin: theta = 2*pi*n/512, n = tid.
    float sn1, cs1;
    sincosf((float)tid * (6.283185307179586f / 512.f), &sn1, &cs1);
    const float c2 = fmaf(cs1, cs1, -(sn1 * sn1));   // cos(2theta)
    const float s2 = 2.f * sn1 * cs1;                // sin(2theta)

    u64 C    = pk(1.f, cs1);      // (cos(k*theta), cos((k+1)*theta)) at k=0
    u64 NS   = pk(0.f, -sn1);     // (-sin(k*theta), -sin((k+1)*theta))
    const u64 CS2  = pk(c2, c2);
    const u64 SN2  = pk(s2, s2);
    const u64 NSN2 = pk(-s2, -s2);
    u64 acc1 = pk(0.f, 0.f);
    u64 acc2 = pk(0.f, 0.f);

    const u64* vfr = (const u64*)sfRe;
    const u64* vfi = (const u64*)sfIm;
    const u64* vpr = (const u64*)spRe;
    const u64* vpi = (const u64*)spIm;

#pragma unroll 4
    for (int kp = 0; kp < 129; kp++) {
        const u64 fr = vfr[kp];
        const u64 fi = vfi[kp];
        const u64 pr = vpr[kp];
        const u64 pi = vpi[kp];
        FMA2(acc1, fr, C,  acc1);   // + Re * cos
        FMA2(acc1, fi, NS, acc1);   // - Im * sin
        FMA2(acc2, pr, C,  acc2);
        FMA2(acc2, pi, NS, acc2);
        u64 t1, t2, Cn, NSn;
        MUL2(t1, NS, SN2);          // -s * sin2t
        MUL2(t2, C,  NSN2);         // -c * sin2t
        FMA2(Cn,  C,  CS2, t1);     // c' = c*cos2t - s*sin2t
        FMA2(NSn, NS, CS2, t2);     // -s' = -s*cos2t - c*sin2t
        C = Cn; NS = NSn;
    }

    float a1l, a1h, a2l, a2h;
    upk(acc1, a1l, a1h);
    upk(acc2, a2l, a2h);
    const float acc1s = a1l + a1h;
    const float acc2s = a2l + a2h;

    // numpy.hanning(512)[n] = 0.5 - 0.5 cos(2 pi n / 511)
    const float h1 = 0.5f - 0.5f * cosf((float)tid         * (6.283185307179586f / 511.f));
    const float h2 = 0.5f - 0.5f * cosf((float)(tid + 256) * (6.283185307179586f / 511.f));

    out[(size_t)b * NSAMP + j * STEP + tid] = acc1s * h1 + acc2s * h2;
}

// ---------------------------------------------------------------------------
// Kernel C: deterministic per-batch sum of squares -> 1/(||x|| + 1e-8)
// ---------------------------------------------------------------------------
__global__ void __launch_bounds__(256) kC(const float* __restrict__ out) {
    __shared__ float red[256];
    const int b = blockIdx.x, tid = threadIdx.x;
    const float4* p = (const float4*)(out + (size_t)b * NSAMP);
    float acc = 0.f;
    for (int i = tid; i < NSAMP / 4; i += 256) {
        const float4 v = p[i];
        acc = fmaf(v.x, v.x, acc);
        acc = fmaf(v.y, v.y, acc);
        acc = fmaf(v.z, v.z, acc);
        acc = fmaf(v.w, v.w, acc);
    }
    red[tid] = acc;
    __syncthreads();
    for (int off = 128; off > 0; off >>= 1) {
        if (tid < off) red[tid] += red[tid + off];
        __syncthreads();
    }
    if (tid == 0) g_inv[b] = 1.f / (sqrtf(red[0]) + 1e-8f);
}

// ---------------------------------------------------------------------------
// Kernel D: scale in place (float4 vectorized)
// ---------------------------------------------------------------------------
__global__ void __launch_bounds__(256) kD(float4* __restrict__ out) {
    const size_t idx = (size_t)blockIdx.x * 256 + threadIdx.x;
    const float s = g_inv[idx >> 13];   // 8192 float4 per batch
    float4 v = out[idx];
    v.x *= s; v.y *= s; v.z *= s; v.w *= s;
    out[idx] = v;
}

extern "C" void kernel_launch(void* const* d_in, const int* in_sizes, int n_in,
                              void* d_out, int out_size) {
    const float* sel   = (const float*)d_in[0];
    const float* items = (const float*)d_in[1];
    // Defensive: identify inputs by element count (sel=512*512, items=512*771)
    if (n_in >= 2 && in_sizes[0] == 512 * 771) {
        items = (const float*)d_in[0];
        sel   = (const float*)d_in[1];
    }
    float* out = (float*)d_out;

    kA<<<NB / BPB, 288>>>(sel, items);
    kB<<<dim3(NFRAMES, NB), 256>>>(out);
    kC<<<NB, 256>>>(out);
    kD<<<(NB * NSAMP) / 1024, 256>>>((float4*)out);
}

// round 3
// speedup vs baseline: 2.6069x; 2.6069x over previous
#include <cuda_runtime.h>
#include <cuda_bf16.h>
#include <math.h>

#define NB      512
#define CHUNK   257
#define NCOEF   771
#define NFRAMES 128
#define STEP    256
#define NSAMP   32768

#define KSEG    1056            // padded per-segment K (1028 used + 28 zero)
#define AK      (2*KSEG)        // A_cat cols: [hi | lo]
#define BROWS   (3*KSEG)        // B_cat rows: [Bh ; Bl ; Bh]
#define MROWS   (NB*NFRAMES)    // 65536
#define NCHUNK  99              // 3 segments * 33 chunks of 32

// Scratch (__device__ globals; no allocation allowed)
__device__ __nv_bfloat16 g_A[(size_t)MROWS * AK];      // ~276.8 MB
__device__ __nv_bfloat16 g_B[(size_t)BROWS * 256];     // ~1.6 MB
__device__ float         g_inv[NB];

// ---------------------------------------------------------------------------
// kZero: zero the K-padding columns of A (cols 1028..1055 hi, 2084..2111 lo)
// ---------------------------------------------------------------------------
__global__ void __launch_bounds__(256) kZero() {
    const int idx = blockIdx.x * 256 + threadIdx.x;     // 65536*28 u32 writes
    const int r = idx / 28, q = idx % 28;
    unsigned int* p = (unsigned int*)g_A;
    const size_t base = (size_t)r * AK;
    if (q < 14) p[(base + 1028) / 2 + q] = 0u;
    else        p[(base + 2084) / 2 + (q - 14)] = 0u;
}

// ---------------------------------------------------------------------------
// kBasis: build B_cat [3168][256].
// Within a 1056 block, row rr:
//   rr in [0,514):    k=rr>>1, trig = (rr&1)? -sin : cos, window h1(n)=hann[n]
//   rr in [514,1028): k=(rr-514)>>1, same trig select, window h2(n)=hann[n+256]
//   rr in [1028,1056): 0
// Rows [0,1056)=hi(v), [1056,2112)=lo(v), [2112,3168)=hi(v).
// ---------------------------------------------------------------------------
__global__ void __launch_bounds__(256) kBasis() {
    const int row = blockIdx.x;        // 0..3167
    const int n   = threadIdx.x;       // 0..255
    const int region = row / KSEG;     // 0=hi, 1=lo, 2=hi
    const int rr = row - region * KSEG;

    float v = 0.f;
    if (rr < 1028) {
        int k, hoff;
        if (rr < 514) { k = rr >> 1;         hoff = n; }
        else          { k = (rr - 514) >> 1; hoff = n + 256; }
        const int p = (k * n) & 511;                       // exact phase mod 512
        float sn, cs;
        sincosf((float)p * (6.283185307179586f / 512.f), &sn, &cs);
        const int odd = (rr < 514) ? (rr & 1) : ((rr - 514) & 1);
        const float trig = odd ? -sn : cs;
        const float h = 0.5f - 0.5f * cosf((float)hoff * (6.283185307179586f / 511.f));
        v = trig * h;
    }
    const __nv_bfloat16 hi = __float2bfloat16(v);
    __nv_bfloat16 res;
    if (region == 1) res = __float2bfloat16(v - __bfloat162float(hi));
    else             res = hi;
    g_B[(size_t)row * 256 + n] = res;
}

// ---------------------------------------------------------------------------
// kA: GEMM (relu(sel) @ items) fused with activations + per-frame complex
// rotator recurrence; writes the hi/lo bf16 A matrix directly.
// Thread = spectral bin k, BPB batches per CTA.
// ---------------------------------------------------------------------------
#define BPB 8
__global__ void __launch_bounds__(288) kA(const float* __restrict__ sel,
                                          const float* __restrict__ items) {
    __shared__ float sh_sel[BPB * 512];
    const int tid = threadIdx.x;
    const int b0  = blockIdx.x * BPB;

    for (int idx = tid; idx < BPB * 512; idx += 288) {
        float v = sel[b0 * 512 + idx];
        sh_sel[idx] = v > 0.f ? v : 0.f;
    }
    __syncthreads();

    const int k = tid;
    if (k >= CHUNK) return;

    float am[BPB], ap[BPB], as_[BPB];
#pragma unroll
    for (int b = 0; b < BPB; b++) { am[b] = 0.f; ap[b] = 0.f; as_[b] = 0.f; }

    for (int i = 0; i < 512; i++) {
        const float i0 = items[i * NCOEF + k];
        const float i1 = items[i * NCOEF + CHUNK + k];
        const float i2 = items[i * NCOEF + 2 * CHUNK + k];
#pragma unroll
        for (int b = 0; b < BPB; b++) {
            const float s = sh_sel[b * 512 + i];
            am[b]  = fmaf(s, i0, am[b]);
            ap[b]  = fmaf(s, i1, ap[b]);
            as_[b] = fmaf(s, i2, as_[b]);
        }
    }

    const float w = (k == 0 || k == 256) ? (1.f / 512.f) : (2.f / 512.f);
    const unsigned int sgnmask = (k & 1) ? 0x80008000u : 0u;
    unsigned int* pA = (unsigned int*)g_A;

#pragma unroll 1
    for (int b = 0; b < BPB; b++) {
        const float m  = fmaf(1.f / (1.f + expf(-am[b])), 0.9999f * 0.5f, 0.5f);
        const float ph = tanhf(ap[b]) * 3.14159265358979323846f;
        const float st = 1.f / (1.f + expf(-as_[b]));
        float sn, cs;
        sincosf(ph, &sn, &cs);
        const float rRe = m * cs, rIm = m * sn;
        float cRe = st * rRe, cIm = st * rIm;       // t=1 term

        const size_t rowBase = ((size_t)(b0 + b) * NFRAMES) * AK;
        // j=0 has no previous frame: zero its shifted slots
        pA[(rowBase + 514 + 2 * k) / 2] = 0u;
        pA[(rowBase + KSEG + 514 + 2 * k) / 2] = 0u;

        for (int f = 0; f < NFRAMES; f++) {
            const float re = w * cRe, im = w * cIm;
            const __nv_bfloat162 hi2 = __floats2bfloat162_rn(re, im);
            const float2 hif = __bfloat1622float2(hi2);
            const __nv_bfloat162 lo2 = __floats2bfloat162_rn(re - hif.x, im - hif.y);
            const unsigned int hiu = *(const unsigned int*)&hi2;
            const unsigned int lou = *(const unsigned int*)&lo2;

            const size_t r = rowBase + (size_t)f * AK;
            pA[(r + 2 * k) / 2]        = hiu;               // current-frame slot
            pA[(r + KSEG + 2 * k) / 2] = lou;
            if (f + 1 < NFRAMES) {                           // shifted slot in row f+1
                const size_t r2 = r + AK;
                pA[(r2 + 514 + 2 * k) / 2]        = hiu ^ sgnmask;
                pA[(r2 + KSEG + 514 + 2 * k) / 2] = lou ^ sgnmask;
            }
            const float nRe = fmaf(cRe, rRe, -(cIm * rIm));
            const float nIm = fmaf(cRe, rIm,  (cIm * rRe));
            cRe = nRe; cIm = nIm;
        }
    }
}

// ---------------------------------------------------------------------------
// kG: bf16 mma.sync GEMM. C[65536,256] = sum of 3 segments:
//   Ah*Bh + Ah*Bl + Al*Bh   (chunk c: 0..32 -> (Ah,Bh), 33..65 -> (Ah,Bl),
//                            66..98 -> (Al,Bh-dup))
// CTA tile 128x128, BK=32, 8 warps (2x4) of 64x32, cp.async double buffer.
// ---------------------------------------------------------------------------
#define LDA_S 40
#define LDB_S 136

__device__ __forceinline__ void cpa16(unsigned int s, const void* g) {
    asm volatile("cp.async.cg.shared.global [%0],[%1],16;" :: "r"(s), "l"(g));
}
__device__ __forceinline__ void ldm4(unsigned int& r0, unsigned int& r1,
                                     unsigned int& r2, unsigned int& r3, unsigned int a) {
    asm volatile("ldmatrix.sync.aligned.m8n8.x4.shared.b16 {%0,%1,%2,%3},[%4];"
                 : "=r"(r0), "=r"(r1), "=r"(r2), "=r"(r3) : "r"(a));
}
__device__ __forceinline__ void ldm4t(unsigned int& r0, unsigned int& r1,
                                      unsigned int& r2, unsigned int& r3, unsigned int a) {
    asm volatile("ldmatrix.sync.aligned.m8n8.x4.trans.shared.b16 {%0,%1,%2,%3},[%4];"
                 : "=r"(r0), "=r"(r1), "=r"(r2), "=r"(r3) : "r"(a));
}
__device__ __forceinline__ void mma16816(float* c, const unsigned int* a, const unsigned int* b) {
    asm volatile("mma.sync.aligned.m16n8k16.row.col.f32.bf16.bf16.f32 "
                 "{%0,%1,%2,%3},{%4,%5,%6,%7},{%8,%9},{%0,%1,%2,%3};"
                 : "+f"(c[0]), "+f"(c[1]), "+f"(c[2]), "+f"(c[3])
                 : "r"(a[0]), "r"(a[1]), "r"(a[2]), "r"(a[3]), "r"(b[0]), "r"(b[1]));
}

__global__ void __launch_bounds__(256) kG(float* __restrict__ out) {
    __shared__ __nv_bfloat16 sA[2][128 * LDA_S];
    __shared__ __nv_bfloat16 sB[2][32 * LDB_S];

    const int tid   = threadIdx.x;
    const int lane  = tid & 31;
    const int wid   = tid >> 5;
    const int warpM = wid >> 2;           // 0..1
    const int warpN = wid & 3;            // 0..3
    const int mBase = blockIdx.x * 128;
    const int nBase = blockIdx.y * 128;

    const unsigned int sA0 = (unsigned int)__cvta_generic_to_shared(&sA[0][0]);
    const unsigned int sA1 = (unsigned int)__cvta_generic_to_shared(&sA[1][0]);
    const unsigned int sB0 = (unsigned int)__cvta_generic_to_shared(&sB[0][0]);
    const unsigned int sB1 = (unsigned int)__cvta_generic_to_shared(&sB[1][0]);

    const int aRow = tid >> 2, aOff = (tid & 3) * 8;
    const int bRow = tid >> 4, bOff = (tid & 15) * 8;

    const __nv_bfloat16* A = g_A;
    const __nv_bfloat16* B = g_B;

    float c[4][4][4];
#pragma unroll
    for (int i = 0; i < 4; i++)
#pragma unroll
        for (int j = 0; j < 4; j++)
#pragma unroll
            for (int q = 0; q < 4; q++) c[i][j][q] = 0.f;

    // ldmatrix lane addressing
    const int lrow  = (lane & 7) + ((lane >> 3) & 1) * 8;  // 0..15
    const int lcol8 = (lane >> 4) * 8;                      // 0 or 8

#define PREFETCH(cIdx, sa, sb)                                                        \
    {                                                                                 \
        const int c_ = (cIdx);                                                        \
        const int cc = (c_ < 33) ? c_ : (c_ < 66 ? c_ - 33 : c_ - 66);                \
        const int aCol = cc * 32 + ((c_ >= 66) ? KSEG : 0);                           \
        const int bR   = c_ * 32;                                                     \
        cpa16((sa) + (unsigned)(aRow * LDA_S + aOff) * 2,                             \
              A + (size_t)(mBase + aRow) * AK + aCol + aOff);                         \
        cpa16((sa) + (unsigned)((aRow + 64) * LDA_S + aOff) * 2,                      \
              A + (size_t)(mBase + aRow + 64) * AK + aCol + aOff);                    \
        cpa16((sb) + (unsigned)(bRow * LDB_S + bOff) * 2,                             \
              B + (size_t)(bR + bRow) * 256 + nBase + bOff);                          \
        cpa16((sb) + (unsigned)((bRow + 16) * LDB_S + bOff) * 2,                      \
              B + (size_t)(bR + bRow + 16) * 256 + nBase + bOff);                     \
        asm volatile("cp.async.commit_group;");                                       \
    }

    PREFETCH(0, sA0, sB0)

    for (int ch = 0; ch < NCHUNK; ch++) {
        const int s = ch & 1;
        const unsigned int sAcur = s ? sA1 : sA0;
        const unsigned int sBcur = s ? sB1 : sB0;
        if (ch + 1 < NCHUNK) {
            const unsigned int sAn = s ? sA0 : sA1;
            const unsigned int sBn = s ? sB0 : sB1;
            PREFETCH(ch + 1, sAn, sBn)
            asm volatile("cp.async.wait_group 1;");
        } else {
            asm volatile("cp.async.wait_group 0;");
        }
        __syncthreads();

#pragma unroll
        for (int kk = 0; kk < 32; kk += 16) {
            unsigned int af[4][4];
#pragma unroll
            for (int mi = 0; mi < 4; mi++) {
                const unsigned int addr = sAcur +
                    (unsigned)((warpM * 64 + mi * 16 + lrow) * LDA_S + kk + lcol8) * 2;
                ldm4(af[mi][0], af[mi][1], af[mi][2], af[mi][3], addr);
            }
            unsigned int bf[4][2];
#pragma unroll
            for (int nj = 0; nj < 2; nj++) {
                const unsigned int addr = sBcur +
                    (unsigned)((kk + lrow) * LDB_S + warpN * 32 + nj * 16 + lcol8) * 2;
                unsigned int r0, r1, r2, r3;
                ldm4t(r0, r1, r2, r3, addr);
                bf[nj * 2][0] = r0; bf[nj * 2][1] = r1;
                bf[nj * 2 + 1][0] = r2; bf[nj * 2 + 1][1] = r3;
            }
#pragma unroll
            for (int mi = 0; mi < 4; mi++)
#pragma unroll
                for (int nf = 0; nf < 4; nf++)
                    mma16816(c[mi][nf], af[mi], bf[nf]);
        }
        __syncthreads();
    }

    // Epilogue: C row r maps to out + r*256 exactly.
#pragma unroll
    for (int mi = 0; mi < 4; mi++) {
#pragma unroll
        for (int nf = 0; nf < 4; nf++) {
            const int r = mBase + warpM * 64 + mi * 16 + (lane >> 2);
            const int n = nBase + warpN * 32 + nf * 8 + (lane & 3) * 2;
            float2* p0 = (float2*)(out + (size_t)r * 256 + n);
            float2* p1 = (float2*)(out + (size_t)(r + 8) * 256 + n);
            *p0 = make_float2(c[mi][nf][0], c[mi][nf][1]);
            *p1 = make_float2(c[mi][nf][2], c[mi][nf][3]);
        }
    }
#undef PREFETCH
}

// ---------------------------------------------------------------------------
// kC: per-batch sum of squares -> 1/(||x|| + 1e-8)
// ---------------------------------------------------------------------------
__global__ void __launch_bounds__(256) kC(const float* __restrict__ out) {
    __shared__ float red[256];
    const int b = blockIdx.x, tid = threadIdx.x;
    const float4* p = (const float4*)(out + (size_t)b * NSAMP);
    float acc = 0.f;
    for (int i = tid; i < NSAMP / 4; i += 256) {
        const float4 v = p[i];
        acc = fmaf(v.x, v.x, acc);
        acc = fmaf(v.y, v.y, acc);
        acc = fmaf(v.z, v.z, acc);
        acc = fmaf(v.w, v.w, acc);
    }
    red[tid] = acc;
    __syncthreads();
    for (int off = 128; off > 0; off >>= 1) {
        if (tid < off) red[tid] += red[tid + off];
        __syncthreads();
    }
    if (tid == 0) g_inv[b] = 1.f / (sqrtf(red[0]) + 1e-8f);
}

// ---------------------------------------------------------------------------
// kD: scale in place
// ---------------------------------------------------------------------------
__global__ void __launch_bounds__(256) kD(float4* __restrict__ out) {
    const size_t idx = (size_t)blockIdx.x * 256 + threadIdx.x;
    const float s = g_inv[idx >> 13];
    float4 v = out[idx];
    v.x *= s; v.y *= s; v.z *= s; v.w *= s;
    out[idx] = v;
}

extern "C" void kernel_launch(void* const* d_in, const int* in_sizes, int n_in,
                              void* d_out, int out_size) {
    const float* sel   = (const float*)d_in[0];
    const float* items = (const float*)d_in[1];
    if (n_in >= 2 && in_sizes[0] == 512 * 771) {
        items = (const float*)d_in[0];
        sel   = (const float*)d_in[1];
    }
    float* out = (float*)d_out;

    kZero<<<(MROWS * 28) / 256, 256>>>();
    kBasis<<<BROWS, 256>>>();
    kA<<<NB / BPB, 288>>>(sel, items);
    kG<<<dim3(MROWS / 128, 2), 256>>>(out);
    kC<<<NB, 256>>>(out);
    kD<<<(NB * NSAMP) / 1024, 256>>>((float4*)out);
}

// round 4
// speedup vs baseline: 3.0633x; 1.1751x over previous
#include <cuda_runtime.h>
#include <cuda_bf16.h>
#include <math.h>

#define NB      512
#define CHUNK   257
#define NCOEF   771
#define NFRAMES 128
#define STEP    256
#define NSAMP   32768

#define KSEG    1056            // padded per-segment K (1028 used + 28 zero)
#define AK      (2*KSEG)        // A_cat cols: [hi | lo]
#define BROWS   (3*KSEG)        // B_cat rows: [Bh ; Bl ; Bh]
#define MROWS   (NB*NFRAMES)    // 65536
#define NCHUNK  99              // 3 segments * 33 chunks of 32
#define NSEG    8               // recurrence segments
#define FSEG    (NFRAMES/NSEG)  // 16 frames per segment

// Scratch (__device__ globals; no allocation allowed)
__device__ __nv_bfloat16 g_A[(size_t)MROWS * AK];      // ~276.8 MB
__device__ __nv_bfloat16 g_B[(size_t)BROWS * 256];     // ~1.6 MB
__device__ float4        g_par[NB * CHUNK];            // (rRe,rIm,c0Re,c0Im)
__device__ float         g_ss[NB];
__device__ float         g_inv[NB];

// ---------------------------------------------------------------------------
// kZero: zero K-padding columns of A + zero g_ss
// ---------------------------------------------------------------------------
__global__ void __launch_bounds__(256) kZero() {
    const int idx = blockIdx.x * 256 + threadIdx.x;     // 65536*28 u32 writes
    if (idx < NB) g_ss[idx] = 0.f;
    const int r = idx / 28, q = idx % 28;
    unsigned int* p = (unsigned int*)g_A;
    const size_t base = (size_t)r * AK;
    if (q < 14) p[(base + 1028) / 2 + q] = 0u;
    else        p[(base + 2084) / 2 + (q - 14)] = 0u;
}

// ---------------------------------------------------------------------------
// kBasis: build B_cat [3168][256] (DFT basis with Hann folded, hi/lo split)
// ---------------------------------------------------------------------------
__global__ void __launch_bounds__(256) kBasis() {
    const int row = blockIdx.x;        // 0..3167
    const int n   = threadIdx.x;       // 0..255
    const int region = row / KSEG;     // 0=hi, 1=lo, 2=hi
    const int rr = row - region * KSEG;

    float v = 0.f;
    if (rr < 1028) {
        int k, hoff;
        if (rr < 514) { k = rr >> 1;         hoff = n; }
        else          { k = (rr - 514) >> 1; hoff = n + 256; }
        const int p = (k * n) & 511;
        float sn, cs;
        sincosf((float)p * (6.283185307179586f / 512.f), &sn, &cs);
        const int odd = (rr < 514) ? (rr & 1) : ((rr - 514) & 1);
        const float trig = odd ? -sn : cs;
        const float h = 0.5f - 0.5f * cosf((float)hoff * (6.283185307179586f / 511.f));
        v = trig * h;
    }
    const __nv_bfloat16 hi = __float2bfloat16(v);
    __nv_bfloat16 res;
    if (region == 1) res = __float2bfloat16(v - __bfloat162float(hi));
    else             res = hi;
    g_B[(size_t)row * 256 + n] = res;
}

// ---------------------------------------------------------------------------
// kP1: selection GEMM + activations -> per-(b,k) rotator params.
// ---------------------------------------------------------------------------
#define BPB 8
__global__ void __launch_bounds__(288) kP1(const float* __restrict__ sel,
                                           const float* __restrict__ items) {
    __shared__ float sh_sel[BPB * 512];
    const int tid = threadIdx.x;
    const int b0  = blockIdx.x * BPB;

    for (int idx = tid; idx < BPB * 512; idx += 288) {
        float v = sel[b0 * 512 + idx];
        sh_sel[idx] = v > 0.f ? v : 0.f;
    }
    __syncthreads();

    const int k = tid;
    if (k >= CHUNK) return;

    float am[BPB], ap[BPB], as_[BPB];
#pragma unroll
    for (int b = 0; b < BPB; b++) { am[b] = 0.f; ap[b] = 0.f; as_[b] = 0.f; }

    for (int i = 0; i < 512; i++) {
        const float i0 = items[i * NCOEF + k];
        const float i1 = items[i * NCOEF + CHUNK + k];
        const float i2 = items[i * NCOEF + 2 * CHUNK + k];
#pragma unroll
        for (int b = 0; b < BPB; b++) {
            const float s = sh_sel[b * 512 + i];
            am[b]  = fmaf(s, i0, am[b]);
            ap[b]  = fmaf(s, i1, ap[b]);
            as_[b] = fmaf(s, i2, as_[b]);
        }
    }

    const float w = (k == 0 || k == 256) ? (1.f / 512.f) : (2.f / 512.f);
#pragma unroll 1
    for (int b = 0; b < BPB; b++) {
        const float m  = fmaf(1.f / (1.f + expf(-am[b])), 0.9999f * 0.5f, 0.5f);
        const float ph = tanhf(ap[b]) * 3.14159265358979323846f;
        const float st = 1.f / (1.f + expf(-as_[b]));
        float sn, cs;
        sincosf(ph, &sn, &cs);
        const float rRe = m * cs, rIm = m * sn;
        const float ws  = w * st;
        g_par[(b0 + b) * CHUNK + k] =
            make_float4(rRe, rIm, ws * rRe, ws * rIm);   // c0 = w*st*r (frame 0)
    }
}

// ---------------------------------------------------------------------------
// kP2: segment-parallel rotator recurrence -> write hi/lo bf16 A matrix.
// grid (NB, NSEG), 288 threads; thread = bin k, handles FSEG frames.
// ---------------------------------------------------------------------------
__device__ __forceinline__ float2 cmul(float2 a, float2 b) {
    return make_float2(fmaf(a.x, b.x, -(a.y * b.y)), fmaf(a.x, b.y, a.y * b.x));
}
__device__ __forceinline__ float2 csq(float2 a) {
    return make_float2(fmaf(a.x, a.x, -(a.y * a.y)), 2.f * a.x * a.y);
}

__global__ void __launch_bounds__(288) kP2() {
    const int k = threadIdx.x;
    if (k >= CHUNK) return;
    const int b = blockIdx.x;
    const int s = blockIdx.y;

    const float4 p = g_par[b * CHUNK + k];
    const float2 r = make_float2(p.x, p.y);
    float2 c = make_float2(p.z, p.w);

    // advance c by r^(16*s) via squarings
    float2 t = csq(csq(csq(csq(r))));   // r^16
    if (s & 1) c = cmul(c, t);
    t = csq(t);                          // r^32
    if (s & 2) c = cmul(c, t);
    t = csq(t);                          // r^64
    if (s & 4) c = cmul(c, t);

    const unsigned int sgnmask = (k & 1) ? 0x80008000u : 0u;
    unsigned int* pA = (unsigned int*)g_A;
    const size_t rowBase = (size_t)(b * NFRAMES) * AK;

    if (s == 0) {   // frame 0 has no previous frame: zero its shifted slots
        pA[(rowBase + 514 + 2 * k) / 2] = 0u;
        pA[(rowBase + KSEG + 514 + 2 * k) / 2] = 0u;
    }

#pragma unroll 1
    for (int i = 0; i < FSEG; i++) {
        const int f = s * FSEG + i;
        const __nv_bfloat162 hi2 = __floats2bfloat162_rn(c.x, c.y);
        const float2 hif = __bfloat1622float2(hi2);
        const __nv_bfloat162 lo2 = __floats2bfloat162_rn(c.x - hif.x, c.y - hif.y);
        const unsigned int hiu = *(const unsigned int*)&hi2;
        const unsigned int lou = *(const unsigned int*)&lo2;

        const size_t rw = rowBase + (size_t)f * AK;
        pA[(rw + 2 * k) / 2]        = hiu;
        pA[(rw + KSEG + 2 * k) / 2] = lou;
        if (f + 1 < NFRAMES) {
            const size_t r2 = rw + AK;
            pA[(r2 + 514 + 2 * k) / 2]        = hiu ^ sgnmask;
            pA[(r2 + KSEG + 514 + 2 * k) / 2] = lou ^ sgnmask;
        }
        c = cmul(c, r);
    }
}

// ---------------------------------------------------------------------------
// kG: bf16 mma.sync GEMM, 4-stage cp.async pipeline, fused ||.||^2 reduce.
// ---------------------------------------------------------------------------
#define LDA_S 40
#define LDB_S 136
#define AS_BYTES (128 * LDA_S * 2)
#define BS_BYTES (32 * LDB_S * 2)
#define SMEM_KG  (4 * (AS_BYTES + BS_BYTES))

__device__ __forceinline__ void cpa16(unsigned int s, const void* g) {
    asm volatile("cp.async.cg.shared.global [%0],[%1],16;" :: "r"(s), "l"(g));
}
__device__ __forceinline__ void ldm4(unsigned int& r0, unsigned int& r1,
                                     unsigned int& r2, unsigned int& r3, unsigned int a) {
    asm volatile("ldmatrix.sync.aligned.m8n8.x4.shared.b16 {%0,%1,%2,%3},[%4];"
                 : "=r"(r0), "=r"(r1), "=r"(r2), "=r"(r3) : "r"(a));
}
__device__ __forceinline__ void ldm4t(unsigned int& r0, unsigned int& r1,
                                      unsigned int& r2, unsigned int& r3, unsigned int a) {
    asm volatile("ldmatrix.sync.aligned.m8n8.x4.trans.shared.b16 {%0,%1,%2,%3},[%4];"
                 : "=r"(r0), "=r"(r1), "=r"(r2), "=r"(r3) : "r"(a));
}
__device__ __forceinline__ void mma16816(float* c, const unsigned int* a, const unsigned int* b) {
    asm volatile("mma.sync.aligned.m16n8k16.row.col.f32.bf16.bf16.f32 "
                 "{%0,%1,%2,%3},{%4,%5,%6,%7},{%8,%9},{%0,%1,%2,%3};"
                 : "+f"(c[0]), "+f"(c[1]), "+f"(c[2]), "+f"(c[3])
                 : "r"(a[0]), "r"(a[1]), "r"(a[2]), "r"(a[3]), "r"(b[0]), "r"(b[1]));
}

__global__ void __launch_bounds__(256, 2) kG(float* __restrict__ out) {
    extern __shared__ __align__(16) __nv_bfloat16 dsm[];
    __shared__ float red[8];

    const int tid   = threadIdx.x;
    const int lane  = tid & 31;
    const int wid   = tid >> 5;
    const int warpM = wid >> 2;
    const int warpN = wid & 3;
    const int mBase = blockIdx.x * 128;
    const int nBase = blockIdx.y * 128;

    const unsigned int base = (unsigned int)__cvta_generic_to_shared(dsm);
#define SA_STAGE(i) (base + (unsigned)(i) * AS_BYTES)
#define SB_STAGE(i) (base + 4u * AS_BYTES + (unsigned)(i) * BS_BYTES)

    const int aRow = tid >> 2, aOff = (tid & 3) * 8;
    const int bRow = tid >> 4, bOff = (tid & 15) * 8;

    const __nv_bfloat16* A = g_A;
    const __nv_bfloat16* B = g_B;

    float c[4][4][4];
#pragma unroll
    for (int i = 0; i < 4; i++)
#pragma unroll
        for (int j = 0; j < 4; j++)
#pragma unroll
            for (int q = 0; q < 4; q++) c[i][j][q] = 0.f;

    const int lrow  = (lane & 7) + ((lane >> 3) & 1) * 8;
    const int lcol8 = (lane >> 4) * 8;

#define PREFETCH(cIdx, st)                                                            \
    {                                                                                 \
        const int c_ = (cIdx);                                                        \
        const int cc = (c_ < 33) ? c_ : (c_ < 66 ? c_ - 33 : c_ - 66);                \
        const int aCol = cc * 32 + ((c_ >= 66) ? KSEG : 0);                           \
        const int bR   = c_ * 32;                                                     \
        const unsigned int sa = SA_STAGE(st);                                         \
        const unsigned int sb = SB_STAGE(st);                                         \
        cpa16(sa + (unsigned)(aRow * LDA_S + aOff) * 2,                               \
              A + (size_t)(mBase + aRow) * AK + aCol + aOff);                         \
        cpa16(sa + (unsigned)((aRow + 64) * LDA_S + aOff) * 2,                        \
              A + (size_t)(mBase + aRow + 64) * AK + aCol + aOff);                    \
        cpa16(sb + (unsigned)(bRow * LDB_S + bOff) * 2,                               \
              B + (size_t)(bR + bRow) * 256 + nBase + bOff);                          \
        cpa16(sb + (unsigned)((bRow + 16) * LDB_S + bOff) * 2,                        \
              B + (size_t)(bR + bRow + 16) * 256 + nBase + bOff);                     \
        asm volatile("cp.async.commit_group;");                                       \
    }

    PREFETCH(0, 0)
    PREFETCH(1, 1)
    PREFETCH(2, 2)

    for (int ch = 0; ch < NCHUNK; ch++) {
        const int stg = ch & 3;
        if (ch + 3 < NCHUNK) {
            asm volatile("cp.async.wait_group 2;");
        } else {
            asm volatile("cp.async.wait_group 0;");
        }
        __syncthreads();
        if (ch + 3 < NCHUNK) PREFETCH(ch + 3, (ch + 3) & 3)

        const unsigned int sAcur = SA_STAGE(stg);
        const unsigned int sBcur = SB_STAGE(stg);
#pragma unroll
        for (int kk = 0; kk < 32; kk += 16) {
            unsigned int af[4][4];
#pragma unroll
            for (int mi = 0; mi < 4; mi++) {
                const unsigned int addr = sAcur +
                    (unsigned)((warpM * 64 + mi * 16 + lrow) * LDA_S + kk + lcol8) * 2;
                ldm4(af[mi][0], af[mi][1], af[mi][2], af[mi][3], addr);
            }
            unsigned int bf[4][2];
#pragma unroll
            for (int nj = 0; nj < 2; nj++) {
                const unsigned int addr = sBcur +
                    (unsigned)((kk + lrow) * LDB_S + warpN * 32 + nj * 16 + lcol8) * 2;
                unsigned int r0, r1, r2, r3;
                ldm4t(r0, r1, r2, r3, addr);
                bf[nj * 2][0] = r0; bf[nj * 2][1] = r1;
                bf[nj * 2 + 1][0] = r2; bf[nj * 2 + 1][1] = r3;
            }
#pragma unroll
            for (int mi = 0; mi < 4; mi++)
#pragma unroll
                for (int nf = 0; nf < 4; nf++)
                    mma16816(c[mi][nf], af[mi], bf[nf]);
        }
    }

    // Epilogue: store C (row r -> out + r*256) and fused sum of squares.
    float ss = 0.f;
#pragma unroll
    for (int mi = 0; mi < 4; mi++) {
#pragma unroll
        for (int nf = 0; nf < 4; nf++) {
            const int r = mBase + warpM * 64 + mi * 16 + (lane >> 2);
            const int n = nBase + warpN * 32 + nf * 8 + (lane & 3) * 2;
            float2* p0 = (float2*)(out + (size_t)r * 256 + n);
            float2* p1 = (float2*)(out + (size_t)(r + 8) * 256 + n);
            *p0 = make_float2(c[mi][nf][0], c[mi][nf][1]);
            *p1 = make_float2(c[mi][nf][2], c[mi][nf][3]);
#pragma unroll
            for (int q = 0; q < 4; q++) ss = fmaf(c[mi][nf][q], c[mi][nf][q], ss);
        }
    }
#pragma unroll
    for (int o = 16; o > 0; o >>= 1) ss += __shfl_xor_sync(0xffffffffu, ss, o);
    if (lane == 0) red[wid] = ss;
    __syncthreads();
    if (tid == 0) {
        float tot = 0.f;
#pragma unroll
        for (int i = 0; i < 8; i++) tot += red[i];
        atomicAdd(&g_ss[blockIdx.x], tot);   // exactly 2 contributors per batch
    }
#undef PREFETCH
#undef SA_STAGE
#undef SB_STAGE
}

// ---------------------------------------------------------------------------
// kN: 512-wide norm finalize
// ---------------------------------------------------------------------------
__global__ void kN() {
    const int i = blockIdx.x * 256 + threadIdx.x;
    if (i < NB) g_inv[i] = 1.f / (sqrtf(g_ss[i]) + 1e-8f);
}

// ---------------------------------------------------------------------------
// kD: scale in place
// ---------------------------------------------------------------------------
__global__ void __launch_bounds__(256) kD(float4* __restrict__ out) {
    const size_t idx = (size_t)blockIdx.x * 256 + threadIdx.x;
    const float s = g_inv[idx >> 13];
    float4 v = out[idx];
    v.x *= s; v.y *= s; v.z *= s; v.w *= s;
    out[idx] = v;
}

extern "C" void kernel_launch(void* const* d_in, const int* in_sizes, int n_in,
                              void* d_out, int out_size) {
    const float* sel   = (const float*)d_in[0];
    const float* items = (const float*)d_in[1];
    if (n_in >= 2 && in_sizes[0] == 512 * 771) {
        items = (const float*)d_in[0];
        sel   = (const float*)d_in[1];
    }
    float* out = (float*)d_out;

    static bool attr_set = false;
    if (!attr_set) {
        cudaFuncSetAttribute(kG, cudaFuncAttributeMaxDynamicSharedMemorySize, SMEM_KG);
        attr_set = true;
    }

    kZero<<<(MROWS * 28) / 256, 256>>>();
    kBasis<<<BROWS, 256>>>();
    kP1<<<NB / BPB, 288>>>(sel, items);
    kP2<<<dim3(NB, NSEG), 288>>>();
    kG<<<dim3(MROWS / 128, 2), 256, SMEM_KG>>>(out);
    kN<<<2, 256>>>();
    kD<<<(NB * NSAMP) / 1024, 256>>>((float4*)out);
}

// round 5
// speedup vs baseline: 3.0851x; 1.0071x over previous
#include <cuda_runtime.h>
#include <cuda_bf16.h>
#include <math.h>

#define NB      512
#define CHUNK   257
#define NFRAMES 128
#define NCOEF   771
#define NSAMP   32768

#define KSEG    1056            // padded per-segment K
#define AK      (2*KSEG)        // A cols: [hi | lo]
#define BROWS   (3*KSEG)        // B rows: [Bh ; Bl ; Bh]
#define MROWS   (NB*NFRAMES)    // 65536
#define NCHUNK  99              // 3 segments * 33 chunks of 32
#define NSEG    8
#define FSEG    (NFRAMES/NSEG)
// Column layout per 1056 segment: [0,514) current, [514,516) zero,
// [516,1030) shifted (u64-aligned), [1030,1056) zero.

__device__ __nv_bfloat16 g_A[(size_t)MROWS * AK];
__device__ __nv_bfloat16 g_B[(size_t)BROWS * 256];
__device__ float4        g_par[NB * CHUNK];
__device__ float         g_ss[NB];
__device__ float         g_inv[NB];

// ---------------------------------------------------------------------------
// kBasis: DFT basis with Hann folded, hi/lo split, new column layout.
// ---------------------------------------------------------------------------
__global__ void __launch_bounds__(256) kBasis() {
    const int row = blockIdx.x;        // 0..3167
    const int n   = threadIdx.x;
    const int region = row / KSEG;     // 0=hi, 1=lo, 2=hi
    const int rr = row - region * KSEG;

    float v = 0.f;
    int k = -1, odd = 0, hoff = 0;
    if (rr < 514)                    { k = rr >> 1;          odd = rr & 1;          hoff = n; }
    else if (rr >= 516 && rr < 1030) { k = (rr - 516) >> 1;  odd = (rr - 516) & 1;  hoff = n + 256; }
    if (k >= 0) {
        const int p = (k * n) & 511;
        float sn, cs;
        sincosf((float)p * (6.283185307179586f / 512.f), &sn, &cs);
        const float trig = odd ? -sn : cs;
        const float h = 0.5f - 0.5f * cosf((float)hoff * (6.283185307179586f / 511.f));
        v = trig * h;
    }
    const __nv_bfloat16 hi = __float2bfloat16(v);
    __nv_bfloat16 res;
    if (region == 1) res = __float2bfloat16(v - __bfloat162float(hi));
    else             res = hi;
    g_B[(size_t)row * 256 + n] = res;
}

// ---------------------------------------------------------------------------
// kP1: selection GEMM + activations -> per-(b,k) rotator params.
// ---------------------------------------------------------------------------
#define BPB 8
__global__ void __launch_bounds__(288) kP1(const float* __restrict__ sel,
                                           const float* __restrict__ items) {
    __shared__ float sh_sel[BPB * 512];
    const int tid = threadIdx.x;
    const int b0  = blockIdx.x * BPB;

    if (blockIdx.x < 2) {            // fold g_ss zeroing
        const int z = blockIdx.x * 288 + tid;
        if (z < NB) g_ss[z] = 0.f;
    }

    for (int idx = tid; idx < BPB * 512; idx += 288) {
        float v = sel[b0 * 512 + idx];
        sh_sel[idx] = v > 0.f ? v : 0.f;
    }
    __syncthreads();

    const int k = tid;
    if (k >= CHUNK) return;

    float am[BPB], ap[BPB], as_[BPB];
#pragma unroll
    for (int b = 0; b < BPB; b++) { am[b] = 0.f; ap[b] = 0.f; as_[b] = 0.f; }

    for (int i = 0; i < 512; i++) {
        const float i0 = items[i * NCOEF + k];
        const float i1 = items[i * NCOEF + CHUNK + k];
        const float i2 = items[i * NCOEF + 2 * CHUNK + k];
#pragma unroll
        for (int b = 0; b < BPB; b++) {
            const float s = sh_sel[b * 512 + i];
            am[b]  = fmaf(s, i0, am[b]);
            ap[b]  = fmaf(s, i1, ap[b]);
            as_[b] = fmaf(s, i2, as_[b]);
        }
    }

    const float w = (k == 0 || k == 256) ? (1.f / 512.f) : (2.f / 512.f);
#pragma unroll 1
    for (int b = 0; b < BPB; b++) {
        const float m  = fmaf(1.f / (1.f + expf(-am[b])), 0.9999f * 0.5f, 0.5f);
        const float ph = tanhf(ap[b]) * 3.14159265358979323846f;
        const float st = 1.f / (1.f + expf(-as_[b]));
        float sn, cs;
        sincosf(ph, &sn, &cs);
        const float rRe = m * cs, rIm = m * sn;
        const float ws  = w * st;
        g_par[(b0 + b) * CHUNK + k] = make_float4(rRe, rIm, ws * rRe, ws * rIm);
    }
}

// ---------------------------------------------------------------------------
// kP2: segment-parallel rotator recurrence -> hi/lo bf16 A, 64-bit stores.
// Thread t<128: bin pair (2t, 2t+1). t==128: bin 256. t in [129,157): pads.
// ---------------------------------------------------------------------------
__device__ __forceinline__ float2 cmul(float2 a, float2 b) {
    return make_float2(fmaf(a.x, b.x, -(a.y * b.y)), fmaf(a.x, b.y, a.y * b.x));
}
__device__ __forceinline__ float2 csq(float2 a) {
    return make_float2(fmaf(a.x, a.x, -(a.y * a.y)), 2.f * a.x * a.y);
}
__device__ __forceinline__ unsigned int pack_hi(float2 c, __nv_bfloat162& h2) {
    h2 = __floats2bfloat162_rn(c.x, c.y);
    return *(unsigned int*)&h2;
}

__global__ void __launch_bounds__(160) kP2() {
    const int t = threadIdx.x;
    const int b = blockIdx.x;
    const int s = blockIdx.y;
    const size_t rowBase = (size_t)b * NFRAMES * AK;   // bf16 units
    unsigned long long* pA64 = (unsigned long long*)g_A;
    unsigned int*       pA32 = (unsigned int*)g_A;

    if (t < 128) {
        const float4 p0 = g_par[b * CHUNK + 2 * t];
        const float4 p1 = g_par[b * CHUNK + 2 * t + 1];
        const float2 r0 = make_float2(p0.x, p0.y);
        const float2 r1 = make_float2(p1.x, p1.y);
        float2 c0 = make_float2(p0.z, p0.w);
        float2 c1 = make_float2(p1.z, p1.w);

        float2 t0 = csq(csq(csq(csq(r0))));   // r^16
        float2 t1 = csq(csq(csq(csq(r1))));
        if (s & 1) { c0 = cmul(c0, t0); c1 = cmul(c1, t1); }
        t0 = csq(t0); t1 = csq(t1);
        if (s & 2) { c0 = cmul(c0, t0); c1 = cmul(c1, t1); }
        t0 = csq(t0); t1 = csq(t1);
        if (s & 4) { c0 = cmul(c0, t0); c1 = cmul(c1, t1); }

        const unsigned long long sgn = 0x8000800000000000ULL;  // odd bin = high u32
        if (s == 0) {   // frame 0 has no previous frame
            pA64[(rowBase + 516) / 4 + t] = 0ull;
            pA64[(rowBase + KSEG + 516) / 4 + t] = 0ull;
        }
#pragma unroll 1
        for (int i = 0; i < FSEG; i++) {
            const int f = s * FSEG + i;
            __nv_bfloat162 h0, h1;
            const unsigned int h0u = pack_hi(c0, h0);
            const unsigned int h1u = pack_hi(c1, h1);
            const float2 h0f = __bfloat1622float2(h0);
            const float2 h1f = __bfloat1622float2(h1);
            const __nv_bfloat162 l0 = __floats2bfloat162_rn(c0.x - h0f.x, c0.y - h0f.y);
            const __nv_bfloat162 l1 = __floats2bfloat162_rn(c1.x - h1f.x, c1.y - h1f.y);
            const unsigned long long hi =
                (unsigned long long)h0u | ((unsigned long long)h1u << 32);
            const unsigned long long lo =
                (unsigned long long)(*(const unsigned int*)&l0) |
                ((unsigned long long)(*(const unsigned int*)&l1) << 32);

            const size_t rw = rowBase + (size_t)f * AK;
            pA64[rw / 4 + t]          = hi;
            pA64[(rw + KSEG) / 4 + t] = lo;
            if (f + 1 < NFRAMES) {
                const size_t r2 = rw + AK;
                pA64[(r2 + 516) / 4 + t]        = hi ^ sgn;
                pA64[(r2 + KSEG + 516) / 4 + t] = lo ^ sgn;
            }
            c0 = cmul(c0, r0); c1 = cmul(c1, r1);
        }
    } else if (t == 128) {
        // bin 256 (even -> no sign flip), scalar u32 path
        const float4 p = g_par[b * CHUNK + 256];
        const float2 r = make_float2(p.x, p.y);
        float2 c = make_float2(p.z, p.w);
        float2 tt = csq(csq(csq(csq(r))));
        if (s & 1) c = cmul(c, tt);
        tt = csq(tt);
        if (s & 2) c = cmul(c, tt);
        tt = csq(tt);
        if (s & 4) c = cmul(c, tt);
        if (s == 0) {
            pA32[(rowBase + 516 + 512) / 2] = 0u;
            pA32[(rowBase + KSEG + 516 + 512) / 2] = 0u;
        }
#pragma unroll 1
        for (int i = 0; i < FSEG; i++) {
            const int f = s * FSEG + i;
            __nv_bfloat162 h;
            const unsigned int hu = pack_hi(c, h);
            const float2 hf = __bfloat1622float2(h);
            const __nv_bfloat162 l = __floats2bfloat162_rn(c.x - hf.x, c.y - hf.y);
            const unsigned int lu = *(const unsigned int*)&l;
            const size_t rw = rowBase + (size_t)f * AK;
            pA32[(rw + 512) / 2]        = hu;
            pA32[(rw + KSEG + 512) / 2] = lu;
            if (f + 1 < NFRAMES) {
                const size_t r2 = rw + AK;
                pA32[(r2 + 516 + 512) / 2]        = hu;
                pA32[(r2 + KSEG + 516 + 512) / 2] = lu;
            }
            c = cmul(c, r);
        }
    } else if (t < 157) {
        // pad zeroing: 28 u32 per row (cols 514, 1030..1055, + lo copies)
        const int q = t - 129;
        size_t off;
        if (q == 0)       off = 514 / 2;
        else if (q < 14)  off = 1030 / 2 + (q - 1);
        else if (q == 14) off = (KSEG + 514) / 2;
        else              off = (KSEG + 1030) / 2 + (q - 15);
#pragma unroll 1
        for (int i = 0; i < FSEG; i++) {
            const size_t rw = rowBase + (size_t)(s * FSEG + i) * AK;
            pA32[rw / 2 + off] = 0u;
        }
    }
}

// ---------------------------------------------------------------------------
// kG: bf16 mma.sync GEMM, 5-stage cp.async pipeline, fused ||.||^2 reduce.
// grid = (2, 512): adjacent block IDs share the A row-panel -> L2 reuse.
// ---------------------------------------------------------------------------
#define LDA_S 40
#define LDB_S 136
#define AS_BYTES (128 * LDA_S * 2)
#define BS_BYTES (32 * LDB_S * 2)
#define NSTAGE   5
#define SMEM_KG  (NSTAGE * (AS_BYTES + BS_BYTES))

__device__ __forceinline__ void cpa16(unsigned int s, const void* g) {
    asm volatile("cp.async.cg.shared.global [%0],[%1],16;" :: "r"(s), "l"(g));
}
__device__ __forceinline__ void ldm4(unsigned int& r0, unsigned int& r1,
                                     unsigned int& r2, unsigned int& r3, unsigned int a) {
    asm volatile("ldmatrix.sync.aligned.m8n8.x4.shared.b16 {%0,%1,%2,%3},[%4];"
                 : "=r"(r0), "=r"(r1), "=r"(r2), "=r"(r3) : "r"(a));
}
__device__ __forceinline__ void ldm4t(unsigned int& r0, unsigned int& r1,
                                      unsigned int& r2, unsigned int& r3, unsigned int a) {
    asm volatile("ldmatrix.sync.aligned.m8n8.x4.trans.shared.b16 {%0,%1,%2,%3},[%4];"
                 : "=r"(r0), "=r"(r1), "=r"(r2), "=r"(r3) : "r"(a));
}
__device__ __forceinline__ void mma16816(float* c, const unsigned int* a, const unsigned int* b) {
    asm volatile("mma.sync.aligned.m16n8k16.row.col.f32.bf16.bf16.f32 "
                 "{%0,%1,%2,%3},{%4,%5,%6,%7},{%8,%9},{%0,%1,%2,%3};"
                 : "+f"(c[0]), "+f"(c[1]), "+f"(c[2]), "+f"(c[3])
                 : "r"(a[0]), "r"(a[1]), "r"(a[2]), "r"(a[3]), "r"(b[0]), "r"(b[1]));
}

__global__ void __launch_bounds__(256, 2) kG(float* __restrict__ out) {
    extern __shared__ __align__(16) __nv_bfloat16 dsm[];
    __shared__ float red[8];

    const int tid   = threadIdx.x;
    const int lane  = tid & 31;
    const int wid   = tid >> 5;
    const int warpM = wid >> 2;
    const int warpN = wid & 3;
    const int mBase = blockIdx.y * 128;   // row panel (batch)
    const int nBase = blockIdx.x * 128;   // N half

    const unsigned int base = (unsigned int)__cvta_generic_to_shared(dsm);
#define SA_STAGE(i) (base + (unsigned)(i) * AS_BYTES)
#define SB_STAGE(i) (base + (unsigned)NSTAGE * AS_BYTES + (unsigned)(i) * BS_BYTES)

    const int aRow = tid >> 2, aOff = (tid & 3) * 8;
    const int bRow = tid >> 4, bOff = (tid & 15) * 8;

    const __nv_bfloat16* A = g_A;
    const __nv_bfloat16* B = g_B;

    float c[4][4][4];
#pragma unroll
    for (int i = 0; i < 4; i++)
#pragma unroll
        for (int j = 0; j < 4; j++)
#pragma unroll
            for (int q = 0; q < 4; q++) c[i][j][q] = 0.f;

    const int lrow  = (lane & 7) + ((lane >> 3) & 1) * 8;
    const int lcol8 = (lane >> 4) * 8;

#define PREFETCH(cIdx, st)                                                            \
    {                                                                                 \
        const int c_ = (cIdx);                                                        \
        const int cc = (c_ < 33) ? c_ : (c_ < 66 ? c_ - 33 : c_ - 66);                \
        const int aCol = cc * 32 + ((c_ >= 66) ? KSEG : 0);                           \
        const int bR   = c_ * 32;                                                     \
        const unsigned int sa = SA_STAGE(st);                                         \
        const unsigned int sb = SB_STAGE(st);                                         \
        cpa16(sa + (unsigned)(aRow * LDA_S + aOff) * 2,                               \
              A + (size_t)(mBase + aRow) * AK + aCol + aOff);                         \
        cpa16(sa + (unsigned)((aRow + 64) * LDA_S + aOff) * 2,                        \
              A + (size_t)(mBase + aRow + 64) * AK + aCol + aOff);                    \
        cpa16(sb + (unsigned)(bRow * LDB_S + bOff) * 2,                               \
              B + (size_t)(bR + bRow) * 256 + nBase + bOff);                          \
        cpa16(sb + (unsigned)((bRow + 16) * LDB_S + bOff) * 2,                        \
              B + (size_t)(bR + bRow + 16) * 256 + nBase + bOff);                     \
        asm volatile("cp.async.commit_group;");                                       \
    }

    PREFETCH(0, 0)
    PREFETCH(1, 1)
    PREFETCH(2, 2)
    PREFETCH(3, 3)

    int stg = 0;
    for (int ch = 0; ch < NCHUNK; ch++) {
        if (ch + 4 < NCHUNK) {
            asm volatile("cp.async.wait_group 3;");
        } else {
            asm volatile("cp.async.wait_group 0;");
        }
        __syncthreads();
        if (ch + 4 < NCHUNK) {
            int pstg = stg + 4; if (pstg >= NSTAGE) pstg -= NSTAGE;
            PREFETCH(ch + 4, pstg)
        }

        const unsigned int sAcur = SA_STAGE(stg);
        const unsigned int sBcur = SB_STAGE(stg);
#pragma unroll
        for (int kk = 0; kk < 32; kk += 16) {
            unsigned int af[4][4];
#pragma unroll
            for (int mi = 0; mi < 4; mi++) {
                const unsigned int addr = sAcur +
                    (unsigned)((warpM * 64 + mi * 16 + lrow) * LDA_S + kk + lcol8) * 2;
                ldm4(af[mi][0], af[mi][1], af[mi][2], af[mi][3], addr);
            }
            unsigned int bf[4][2];
#pragma unroll
            for (int nj = 0; nj < 2; nj++) {
                const unsigned int addr = sBcur +
                    (unsigned)((kk + lrow) * LDB_S + warpN * 32 + nj * 16 + lcol8) * 2;
                unsigned int r0, r1, r2, r3;
                ldm4t(r0, r1, r2, r3, addr);
                bf[nj * 2][0] = r0; bf[nj * 2][1] = r1;
                bf[nj * 2 + 1][0] = r2; bf[nj * 2 + 1][1] = r3;
            }
#pragma unroll
            for (int mi = 0; mi < 4; mi++)
#pragma unroll
                for (int nf = 0; nf < 4; nf++)
                    mma16816(c[mi][nf], af[mi], bf[nf]);
        }
        if (++stg == NSTAGE) stg = 0;
    }

    float ss = 0.f;
#pragma unroll
    for (int mi = 0; mi < 4; mi++) {
#pragma unroll
        for (int nf = 0; nf < 4; nf++) {
            const int r = mBase + warpM * 64 + mi * 16 + (lane >> 2);
            const int n = nBase + warpN * 32 + nf * 8 + (lane & 3) * 2;
            float2* p0 = (float2*)(out + (size_t)r * 256 + n);
            float2* p1 = (float2*)(out + (size_t)(r + 8) * 256 + n);
            *p0 = make_float2(c[mi][nf][0], c[mi][nf][1]);
            *p1 = make_float2(c[mi][nf][2], c[mi][nf][3]);
#pragma unroll
            for (int q = 0; q < 4; q++) ss = fmaf(c[mi][nf][q], c[mi][nf][q], ss);
        }
    }
#pragma unroll
    for (int o = 16; o > 0; o >>= 1) ss += __shfl_xor_sync(0xffffffffu, ss, o);
    if (lane == 0) red[wid] = ss;
    __syncthreads();
    if (tid == 0) {
        float tot = 0.f;
#pragma unroll
        for (int i = 0; i < 8; i++) tot += red[i];
        atomicAdd(&g_ss[blockIdx.y], tot);   // exactly 2 contributors per batch
    }
#undef PREFETCH
#undef SA_STAGE
#undef SB_STAGE
}

// ---------------------------------------------------------------------------
__global__ void kN() {
    const int i = blockIdx.x * 256 + threadIdx.x;
    if (i < NB) g_inv[i] = 1.f / (sqrtf(g_ss[i]) + 1e-8f);
}

__global__ void __launch_bounds__(256) kD(float4* __restrict__ out) {
    const size_t idx = (size_t)blockIdx.x * 256 + threadIdx.x;
    const float s = g_inv[idx >> 13];
    float4 v = out[idx];
    v.x *= s; v.y *= s; v.z *= s; v.w *= s;
    out[idx] = v;
}

extern "C" void kernel_launch(void* const* d_in, const int* in_sizes, int n_in,
                              void* d_out, int out_size) {
    const float* sel   = (const float*)d_in[0];
    const float* items = (const float*)d_in[1];
    if (n_in >= 2 && in_sizes[0] == 512 * 771) {
        items = (const float*)d_in[0];
        sel   = (const float*)d_in[1];
    }
    float* out = (float*)d_out;

    static bool attr_set = false;
    if (!attr_set) {
        cudaFuncSetAttribute(kG, cudaFuncAttributeMaxDynamicSharedMemorySize, SMEM_KG);
        attr_set = true;
    }

    kBasis<<<BROWS, 256>>>();
    kP1<<<NB / BPB, 288>>>(sel, items);
    kP2<<<dim3(NB, NSEG), 160>>>();
    kG<<<dim3(2, MROWS / 128), 256, SMEM_KG>>>(out);
    kN<<<2, 256>>>();
    kD<<<(NB * NSAMP) / 1024, 256>>>((float4*)out);
}